// round 7
// baseline (speedup 1.0000x reference)
#include <cuda_runtime.h>
#include <cstdint>

typedef unsigned long long u64;
typedef unsigned int u32;

#define HWDIM 224
#define HWPIX (HWDIM*HWDIM)   // 50176
#define NB    16
#define NTOK  49
#define CH    64
#define NOUT  80               // q(0..7) k(8..15) v(16..79)

// scratch: pixel-linear qkv [b][hw][80]
__device__ float g_qkv[(size_t)NB * HWPIX * NOUT];

__device__ __forceinline__ u64 f2swap(u64 v){
    u64 r;
    asm("{\n\t.reg .b32 l,h;\n\tmov.b64 {l,h}, %1;\n\tmov.b64 %0, {h,l};\n\t}"
        : "=l"(r) : "l"(v));
    return r;
}
__device__ __forceinline__ void ffma2(u64 &d, u64 a, u64 b){
    asm("fma.rn.f32x2 %0, %1, %2, %0;" : "+l"(d) : "l"(a), "l"(b));
}
__device__ __forceinline__ float f2lo(u64 v){ return __int_as_float((u32)(v & 0xffffffffull)); }
__device__ __forceinline__ float f2hi(u64 v){ return __int_as_float((u32)(v >> 32)); }

// ===================== K1: fused QKV projection =====================
// 128 threads, 128 pixels/block; tile 8px x 10 outs (diag f32x2).
// smem: xs[64][128]@0 (8192) | wct[64][80]@8192 (5120) | bias@13312 (80)
// epilogue: os1[128][80] overlays [0..10240)
#define K1_SMEM_FLOATS 13392
#define K1_SMEM_BYTES  (K1_SMEM_FLOATS*4)

__global__ void __launch_bounds__(128, 4)
proj_kernel(const float* __restrict__ x,
            const float* __restrict__ Wq, const float* __restrict__ bq,
            const float* __restrict__ Wk, const float* __restrict__ bk,
            const float* __restrict__ Wv, const float* __restrict__ bv)
{
    extern __shared__ float s1[];
    const int tid = threadIdx.x;
    const int blk = blockIdx.x;               // 16 * 392
    const int b   = blk / 392;
    const int hw0 = (blk - b * 392) * 128;

    // stage raw weights [o][c] stride 65 (in xs area, overwritten later)
    for (int idx = tid; idx < 512; idx += 128) {
        int o = idx >> 6, c = idx & 63;
        s1[o * 65 + c]       = __ldg(&Wq[idx]);
        s1[520 + o * 65 + c] = __ldg(&Wk[idx]);
    }
    for (int idx = tid; idx < 4096; idx += 128) {
        int o = idx >> 6, c = idx & 63;
        s1[1040 + o * 65 + c] = __ldg(&Wv[idx]);
    }
    if (tid < 80)
        s1[13312 + tid] = (tid < 8)  ? __ldg(&bq[tid])
                        : (tid < 16) ? __ldg(&bk[tid - 8])
                                     : __ldg(&bv[tid - 16]);
    __syncthreads();
    // transpose -> wct[c][80]: q(0..7) k(8..15) v(16..79)
    for (int idx = tid; idx < 5120; idx += 128) {
        int c = idx / 80, o = idx - c * 80;
        float v = (o < 8)  ? s1[o * 65 + c]
                : (o < 16) ? s1[520 + (o - 8) * 65 + c]
                           : s1[1040 + (o - 16) * 65 + c];
        s1[8192 + c * 80 + o] = v;
    }
    __syncthreads();
    // x tile -> xs[c][p] via float4 (overwrites raw stage)
    const float* xb = x + (size_t)b * CH * HWPIX + hw0;
    for (int idx = tid; idx < 2048; idx += 128) {
        int c = idx >> 5, p4 = idx & 31;
        float4 v = __ldg(reinterpret_cast<const float4*>(xb + (size_t)c * HWPIX) + p4);
        *reinterpret_cast<float4*>(s1 + c * 128 + p4 * 4) = v;
    }
    __syncthreads();

    // compute: tile 8px x 10 outs
    const int og = tid & 7, pg = tid >> 3;
    const int o0 = og * 10, p0 = pg * 8;

    u64 accA[4][5], accB[4][5];
    #pragma unroll
    for (int p = 0; p < 4; p++)
        #pragma unroll
        for (int q = 0; q < 5; q++) { accA[p][q] = 0ull; accB[p][q] = 0ull; }

    const u64* xbase = reinterpret_cast<const u64*>(s1) + (p0 >> 1);
    const u64* wbase = reinterpret_cast<const u64*>(s1 + 8192) + og * 5;

    #pragma unroll 2
    for (int c = 0; c < CH; c++) {
        u64 xv[4];
        #pragma unroll
        for (int p = 0; p < 4; p++) xv[p] = xbase[c * 64 + p];
        #pragma unroll
        for (int q = 0; q < 5; q++) {
            u64 wn = wbase[c * 40 + q];
            u64 ws = f2swap(wn);
            #pragma unroll
            for (int p = 0; p < 4; p++) {
                ffma2(accA[p][q], xv[p], wn);
                ffma2(accB[p][q], xv[p], ws);
            }
        }
    }
    __syncthreads();   // xs/wct reads done; os1 overlays them

    // epilogue stage: os1[p][80] @ s1[0..10240)
    const float* sb = s1 + 13312;
    #pragma unroll
    for (int p = 0; p < 4; p++) {
        int ta = p0 + 2 * p, tb = ta + 1;
        #pragma unroll
        for (int q = 0; q < 5; q++) {
            float b0 = sb[o0 + 2*q], b1 = sb[o0 + 2*q + 1];
            *reinterpret_cast<float2*>(s1 + ta * 80 + o0 + 2*q)
                = make_float2(f2lo(accA[p][q]) + b0, f2lo(accB[p][q]) + b1);
            *reinterpret_cast<float2*>(s1 + tb * 80 + o0 + 2*q)
                = make_float2(f2hi(accB[p][q]) + b0, f2hi(accA[p][q]) + b1);
        }
    }
    __syncthreads();

    // coalesced stream to g_qkv (128px * 80 floats contiguous)
    float4* dst = reinterpret_cast<float4*>(g_qkv + ((size_t)b * HWPIX + hw0) * NOUT);
    const float4* src = reinterpret_cast<const float4*>(s1);
    for (int i = tid; i < 2560; i += 128) dst[i] = src[i];
}

// ===================== K2: windowed attention =====================
// 96 threads, 1 window per block; 8 blocks/SM (24 warps).
// smem (6720 floats): qkv[49][80]@0 (3920) | att[49..51][56]@3920 (2800)
// os[t][66] overlays qkv region (dead after AV compute); t up to 49 fits.
#define ATT_OFF 3920
#define OS_STRIDE 66
#define K2_SMEM_FLOATS 6720
#define K2_SMEM_BYTES  (K2_SMEM_FLOATS*4)   // 26880

__global__ void __launch_bounds__(96, 8)
attn_kernel(const float* __restrict__ x,
            const float* __restrict__ gamma,
            float* __restrict__ out)
{
    extern __shared__ float sp[];
    const int tid = threadIdx.x;
    const int blk = blockIdx.x;        // 16 b * 32 wh * 32 ww
    const int b   = blk >> 10;
    const int rem = blk & 1023;
    const int wh  = rem >> 5;
    const int ww  = rem & 31;
    const int h0  = wh * 7;
    const int w0  = ww * 7;

    const float g = __ldg(gamma);

    // ---- stage qkv: 49 px * 80 floats = 980 float4 ----
    const float* gq = g_qkv + ((size_t)b * HWPIX + (size_t)h0 * HWDIM + w0) * NOUT;
    for (int i = tid; i < 980; i += 96) {
        int ph = i / 140;
        int r  = i - ph * 140;
        int pw = r / 20;
        int c4 = r - pw * 20;
        int t  = ph * 7 + pw;
        float4 v = __ldg(reinterpret_cast<const float4*>(gq + ((size_t)ph * HWDIM + pw) * NOUT) + c4);
        *reinterpret_cast<float4*>(sp + t * NOUT + c4 * 4) = v;
    }
    // zero att pad cols n = 49..55 (AV reads token cols up to 49)
    for (int i = tid; i < 343; i += 96) {
        int m = i / 7, j = i - m * 7;
        sp[ATT_OFF + m * 56 + 49 + j] = 0.0f;
    }
    __syncthreads();

    // ---- logits: attT[m][n] = <q_n, k_m>, tile 7n x 4m, 91 threads ----
    if (tid < 91) {
        int ng = tid / 13, mg = tid - ng * 13;
        int n0 = ng * 7, m0 = mg * 4;
        int mlim = (m0 + 4 <= NTOK) ? 4 : (NTOK - m0);
        float acc[7][4];
        #pragma unroll
        for (int i = 0; i < 7; i++)
            #pragma unroll
            for (int j = 0; j < 4; j++) acc[i][j] = 0.0f;
        #pragma unroll
        for (int c = 0; c < 8; c++) {
            float qv[7], kv[4];
            #pragma unroll
            for (int i = 0; i < 7; i++) qv[i] = sp[(n0 + i) * NOUT + c];
            #pragma unroll
            for (int j = 0; j < 4; j++) kv[j] = sp[(m0 + j) * NOUT + 8 + c];
            #pragma unroll
            for (int i = 0; i < 7; i++)
                #pragma unroll
                for (int j = 0; j < 4; j++) acc[i][j] = fmaf(qv[i], kv[j], acc[i][j]);
        }
        float* atp = sp + ATT_OFF;
        for (int j = 0; j < mlim; j++)
            #pragma unroll
            for (int i = 0; i < 7; i++)
                atp[(m0 + j) * 56 + (n0 + i)] = acc[i][j];
    }
    __syncthreads();

    // ---- softmax over keys m (columns of attT), gamma folded ----
    if (tid < NTOK) {
        float* atp = sp + ATT_OFF + tid;
        float mx = atp[0];
        #pragma unroll 7
        for (int m = 1; m < NTOK; m++) mx = fmaxf(mx, atp[m * 56]);
        float s = 0.0f;
        #pragma unroll 7
        for (int m = 0; m < NTOK; m++) {
            float e = __expf(atp[m * 56] - mx);
            atp[m * 56] = e;
            s += e;
        }
        float rs = g / s;
        #pragma unroll 7
        for (int m = 0; m < NTOK; m++) atp[m * 56] *= rs;
    }
    __syncthreads();

    // ---- AV: out[t][c] = sum_m att[m][t]*v[m][c] ----
    // 12 t-groups x 8 c-groups = 96 tiles; tg 0..10: 2 token-pairs, tg 11: 3 pairs
    const int cg = tid & 7, tg = tid >> 3;
    const int t0 = tg * 4, c0 = cg * 8;
    u64 accA[3][4], accB[3][4];
    #pragma unroll
    for (int p = 0; p < 3; p++)
        #pragma unroll
        for (int q = 0; q < 4; q++) { accA[p][q] = 0ull; accB[p][q] = 0ull; }

    {
        const float* atb = sp + ATT_OFF + t0;
        const float* vb  = sp + 16 + c0;
        if (tg < 11) {
            #pragma unroll 7
            for (int m = 0; m < NTOK; m++) {
                const u64* ar = reinterpret_cast<const u64*>(atb + m * 56);
                const u64* vr = reinterpret_cast<const u64*>(vb + m * NOUT);
                u64 a0 = ar[0], a1 = ar[1];
                #pragma unroll
                for (int q = 0; q < 4; q++) {
                    u64 vn = vr[q];
                    u64 vs = f2swap(vn);
                    ffma2(accA[0][q], a0, vn);
                    ffma2(accB[0][q], a0, vs);
                    ffma2(accA[1][q], a1, vn);
                    ffma2(accB[1][q], a1, vs);
                }
            }
        } else {
            #pragma unroll 7
            for (int m = 0; m < NTOK; m++) {
                const u64* ar = reinterpret_cast<const u64*>(atb + m * 56);
                const u64* vr = reinterpret_cast<const u64*>(vb + m * NOUT);
                u64 a0 = ar[0], a1 = ar[1], a2 = ar[2];  // tokens 44..49 (49 = zero pad)
                #pragma unroll
                for (int q = 0; q < 4; q++) {
                    u64 vn = vr[q];
                    u64 vs = f2swap(vn);
                    ffma2(accA[0][q], a0, vn);
                    ffma2(accB[0][q], a0, vs);
                    ffma2(accA[1][q], a1, vn);
                    ffma2(accB[1][q], a1, vs);
                    ffma2(accA[2][q], a2, vn);
                    ffma2(accB[2][q], a2, vs);
                }
            }
        }
    }
    __syncthreads();   // all att/v reads done before os overlays qkv region

    {
        float* osp = sp;   // os[t][66] over dead qkv
        if (tg < 11) {
            #pragma unroll
            for (int p = 0; p < 2; p++) {
                int ta = t0 + 2 * p, tb = ta + 1;
                #pragma unroll
                for (int q = 0; q < 4; q++) {
                    *reinterpret_cast<float2*>(osp + ta * OS_STRIDE + c0 + 2*q)
                        = make_float2(f2lo(accA[p][q]), f2lo(accB[p][q]));
                    *reinterpret_cast<float2*>(osp + tb * OS_STRIDE + c0 + 2*q)
                        = make_float2(f2hi(accB[p][q]), f2hi(accA[p][q]));
                }
            }
        } else {
            #pragma unroll
            for (int p = 0; p < 3; p++) {
                int ta = t0 + 2 * p, tb = ta + 1;   // up to t=49 (52*66 < 3920, safe)
                #pragma unroll
                for (int q = 0; q < 4; q++) {
                    *reinterpret_cast<float2*>(osp + ta * OS_STRIDE + c0 + 2*q)
                        = make_float2(f2lo(accA[p][q]), f2lo(accB[p][q]));
                    *reinterpret_cast<float2*>(osp + tb * OS_STRIDE + c0 + 2*q)
                        = make_float2(f2hi(accB[p][q]), f2hi(accA[p][q]));
                }
            }
        }
    }
    __syncthreads();

    // ---- residual + store: out = os + x (gamma already applied) ----
    // unit = (pixel, c-half): 98 units over 96 threads
    for (int u = tid; u < 98; u += 96) {
        int p  = u >> 1;
        int ch = (u & 1) * 32;
        int ph = p / 7, pw = p - ph * 7;
        const float* osr = sp + p * OS_STRIDE + ch;
        size_t gi = (size_t)b * CH * HWPIX + (size_t)(h0 + ph) * HWDIM + (w0 + pw)
                  + (size_t)ch * HWPIX;
        #pragma unroll 4
        for (int c = 0; c < 32; c++) {
            out[gi] = osr[c] + __ldg(&x[gi]);
            gi += HWPIX;
        }
    }
}

extern "C" void kernel_launch(void* const* d_in, const int* in_sizes, int n_in,
                              void* d_out, int out_size)
{
    const float* x     = (const float*)d_in[0];
    const float* Wq    = (const float*)d_in[1];
    const float* bq    = (const float*)d_in[2];
    const float* Wk    = (const float*)d_in[3];
    const float* bk    = (const float*)d_in[4];
    const float* Wv    = (const float*)d_in[5];
    const float* bv    = (const float*)d_in[6];
    const float* gamma = (const float*)d_in[7];
    float* out = (float*)d_out;

    cudaFuncSetAttribute(proj_kernel, cudaFuncAttributeMaxDynamicSharedMemorySize, K1_SMEM_BYTES);
    cudaFuncSetAttribute(attn_kernel, cudaFuncAttributeMaxDynamicSharedMemorySize, K2_SMEM_BYTES);

    proj_kernel<<<NB * (HWPIX / 128), 128, K1_SMEM_BYTES>>>(x, Wq, bq, Wk, bk, Wv, bv);
    attn_kernel<<<NB * 1024, 96, K2_SMEM_BYTES>>>(x, gamma, out);
}

// round 8
// speedup vs baseline: 1.2919x; 1.2919x over previous
#include <cuda_runtime.h>
#include <cstdint>

typedef unsigned long long u64;
typedef unsigned int u32;

#define HWDIM 224
#define HWPIX (HWDIM*HWDIM)   // 50176
#define NB    16
#define NTOK  49
#define CH    64
#define NOUT  80               // q(0..7) k(8..15) v(16..79)

// scratch: pixel-linear qkv [b][hw][80]
__device__ float g_qkv[(size_t)NB * HWPIX * NOUT];

__device__ __forceinline__ u64 f2swap(u64 v){
    u64 r;
    asm("{\n\t.reg .b32 l,h;\n\tmov.b64 {l,h}, %1;\n\tmov.b64 %0, {h,l};\n\t}"
        : "=l"(r) : "l"(v));
    return r;
}
__device__ __forceinline__ void ffma2(u64 &d, u64 a, u64 b){
    asm("fma.rn.f32x2 %0, %1, %2, %0;" : "+l"(d) : "l"(a), "l"(b));
}
__device__ __forceinline__ float f2lo(u64 v){ return __int_as_float((u32)(v & 0xffffffffull)); }
__device__ __forceinline__ float f2hi(u64 v){ return __int_as_float((u32)(v >> 32)); }

__device__ __forceinline__ float tf32r(float f){
    u32 r;
    asm("cvt.rna.tf32.f32 %0, %1;" : "=r"(r) : "f"(f));
    return __uint_as_float(r);
}
__device__ __forceinline__ void mma_tf32(float* d, const u32* a, u32 b0, u32 b1){
    asm volatile(
        "mma.sync.aligned.m16n8k8.row.col.f32.tf32.tf32.f32 "
        "{%0,%1,%2,%3}, {%4,%5,%6,%7}, {%8,%9}, {%0,%1,%2,%3};"
        : "+f"(d[0]), "+f"(d[1]), "+f"(d[2]), "+f"(d[3])
        : "r"(a[0]), "r"(a[1]), "r"(a[2]), "r"(a[3]), "r"(b0), "r"(b1));
}

// ===================== K1: fused QKV projection (tf32 tensor cores) ===========
// 128 threads, 128 pixels/block. Warp = 32 px x 80 outs (2 m-tiles x 10 n-tiles).
// smem floats: wct[64][82]@0 (5248, tf32) | xt[128][66]@5248 (8448, tf32) | bias@13696 (80)
// epilogue: os[128][80] overlays [0..10240)
#define WCT_S 82
#define XT_S  66
#define OFF_XT   5248
#define OFF_BIAS 13696
#define K1_SMEM_FLOATS 13776
#define K1_SMEM_BYTES  (K1_SMEM_FLOATS*4)   // 55104

__global__ void __launch_bounds__(128, 4)
proj_kernel(const float* __restrict__ x,
            const float* __restrict__ Wq, const float* __restrict__ bq,
            const float* __restrict__ Wk, const float* __restrict__ bk,
            const float* __restrict__ Wv, const float* __restrict__ bv)
{
    extern __shared__ float s1[];
    const int tid = threadIdx.x;
    const int blk = blockIdx.x;               // 16 * 392
    const int b   = blk / 392;
    const int hw0 = (blk - b * 392) * 128;

    // weights -> wct[c][82], tf32-rounded; cols: q(0..7) k(8..15) v(16..79)
    for (int idx = tid; idx < 512; idx += 128) {
        int o = idx >> 6, c = idx & 63;
        s1[c * WCT_S + o]     = tf32r(__ldg(&Wq[idx]));
        s1[c * WCT_S + 8 + o] = tf32r(__ldg(&Wk[idx]));
    }
    for (int idx = tid; idx < 4096; idx += 128) {
        int o = idx >> 6, c = idx & 63;
        s1[c * WCT_S + 16 + o] = tf32r(__ldg(&Wv[idx]));
    }
    if (tid < 80)
        s1[OFF_BIAS + tid] = (tid < 8)  ? __ldg(&bq[tid])
                           : (tid < 16) ? __ldg(&bk[tid - 8])
                                        : __ldg(&bv[tid - 16]);
    // x tile -> xt[p][66], tf32-rounded (transposed store)
    const float* xb = x + (size_t)b * CH * HWPIX + hw0;
    for (int idx = tid; idx < 2048; idx += 128) {
        int c = idx >> 5, p4 = idx & 31;
        float4 v = __ldg(reinterpret_cast<const float4*>(xb + (size_t)c * HWPIX) + p4);
        float* xp = s1 + OFF_XT + (p4 * 4) * XT_S + c;
        xp[0]        = tf32r(v.x);
        xp[XT_S]     = tf32r(v.y);
        xp[2 * XT_S] = tf32r(v.z);
        xp[3 * XT_S] = tf32r(v.w);
    }
    __syncthreads();

    // compute: warp covers px [wid*32, wid*32+32)
    const int wid  = tid >> 5, lane = tid & 31;
    const int grp  = lane >> 2;        // 0..7
    const int tig  = lane & 3;         // 0..3
    const int pb   = wid * 32;

    float d[2][10][4];
    #pragma unroll
    for (int mt = 0; mt < 2; mt++)
        #pragma unroll
        for (int nt = 0; nt < 10; nt++)
            #pragma unroll
            for (int e = 0; e < 4; e++) d[mt][nt][e] = 0.0f;

    const u32* xtu = reinterpret_cast<const u32*>(s1 + OFF_XT);
    const u32* wcu = reinterpret_cast<const u32*>(s1);

    #pragma unroll
    for (int k0 = 0; k0 < 64; k0 += 8) {
        u32 a[2][4];
        #pragma unroll
        for (int mt = 0; mt < 2; mt++) {
            int base = pb + mt * 16;
            a[mt][0] = xtu[(base + grp)     * XT_S + k0 + tig];
            a[mt][1] = xtu[(base + grp + 8) * XT_S + k0 + tig];
            a[mt][2] = xtu[(base + grp)     * XT_S + k0 + tig + 4];
            a[mt][3] = xtu[(base + grp + 8) * XT_S + k0 + tig + 4];
        }
        #pragma unroll
        for (int nt = 0; nt < 10; nt++) {
            u32 b0 = wcu[(k0 + tig)     * WCT_S + nt * 8 + grp];
            u32 b1 = wcu[(k0 + tig + 4) * WCT_S + nt * 8 + grp];
            mma_tf32(d[0][nt], a[0], b0, b1);
            mma_tf32(d[1][nt], a[1], b0, b1);
        }
    }
    __syncthreads();   // xt/wct reads done; os overlays them

    // epilogue: os[p][80] = d + bias
    const float* sb = s1 + OFF_BIAS;
    #pragma unroll
    for (int mt = 0; mt < 2; mt++) {
        int p0 = pb + mt * 16 + grp;
        #pragma unroll
        for (int nt = 0; nt < 10; nt++) {
            int n0 = nt * 8 + 2 * tig;
            float b0v = sb[n0], b1v = sb[n0 + 1];
            *reinterpret_cast<float2*>(s1 + p0 * 80 + n0)
                = make_float2(d[mt][nt][0] + b0v, d[mt][nt][1] + b1v);
            *reinterpret_cast<float2*>(s1 + (p0 + 8) * 80 + n0)
                = make_float2(d[mt][nt][2] + b0v, d[mt][nt][3] + b1v);
        }
    }
    __syncthreads();

    // coalesced stream to g_qkv (128px * 80 floats contiguous)
    float4* dst = reinterpret_cast<float4*>(g_qkv + ((size_t)b * HWPIX + hw0) * NOUT);
    const float4* src = reinterpret_cast<const float4*>(s1);
    for (int i = tid; i < 2560; i += 128) dst[i] = src[i];
}

// ===================== K2: windowed attention (round-6 fp32 version) ==========
// 128 threads, 2 horizontally-adjacent windows.
// pool/window (6768 floats): qkv[49][80]@0 (3920) | att[49][56]@3920
// os[49][66] overlays the qkv region (dead after AV compute).
#define PW 6768
#define OS_STRIDE 66
#define K2_SMEM_FLOATS (2*PW)
#define K2_SMEM_BYTES  (K2_SMEM_FLOATS*4)   // 54144

__global__ void __launch_bounds__(128, 4)
attn_kernel(const float* __restrict__ x,
            const float* __restrict__ gamma,
            float* __restrict__ out)
{
    extern __shared__ float s2[];
    const int tid = threadIdx.x;
    const int blk = blockIdx.x;        // 16 b * 32 wh * 16 wpair
    const int b   = blk >> 9;
    const int rem = blk & 511;
    const int wh  = rem >> 4;
    const int wp  = rem & 15;
    const int h0  = wh * 7;
    const int w0  = wp * 14;

    const float g = __ldg(gamma);

    // ---- stage qkv: 7 rows of 14px*80 contiguous floats ----
    const float* gq = g_qkv + ((size_t)b * HWPIX + (size_t)h0 * HWDIM + w0) * NOUT;
    for (int i = tid; i < 1960; i += 128) {
        int ph = i / 280;
        int rr = i - ph * 280;
        int pw = rr / 20;
        int c4 = rr - pw * 20;
        int win = (pw >= 7);
        int t   = ph * 7 + pw - 7 * win;
        float4 v = __ldg(reinterpret_cast<const float4*>(gq + ((size_t)ph * HWDIM + pw) * NOUT) + c4);
        *reinterpret_cast<float4*>(s2 + win * PW + t * NOUT + c4 * 4) = v;
    }
    // zero att pad cols n = 49..55
    for (int i = tid; i < 686; i += 128) {
        int win = i / 343;
        int r   = i - win * 343;
        int m   = r / 7, j = r - m * 7;
        s2[win * PW + 3920 + m * 56 + 49 + j] = 0.0f;
    }
    __syncthreads();

    // ---- logits: attT[m][n] = <q_n, k_m>, 7x7 tiles ----
    if (tid < 98) {
        int win = tid / 49;
        int r   = tid - win * 49;
        int n0  = (r / 7) * 7, m0 = (r % 7) * 7;
        const float* pool = s2 + win * PW;
        float acc[7][7];
        #pragma unroll
        for (int i = 0; i < 7; i++)
            #pragma unroll
            for (int j = 0; j < 7; j++) acc[i][j] = 0.0f;
        #pragma unroll
        for (int c = 0; c < 8; c++) {
            float qv[7], kv[7];
            #pragma unroll
            for (int i = 0; i < 7; i++) qv[i] = pool[(n0 + i) * NOUT + c];
            #pragma unroll
            for (int j = 0; j < 7; j++) kv[j] = pool[(m0 + j) * NOUT + 8 + c];
            #pragma unroll
            for (int i = 0; i < 7; i++)
                #pragma unroll
                for (int j = 0; j < 7; j++) acc[i][j] = fmaf(qv[i], kv[j], acc[i][j]);
        }
        float* atp = s2 + win * PW + 3920;
        #pragma unroll
        for (int i = 0; i < 7; i++)
            #pragma unroll
            for (int j = 0; j < 7; j++)
                atp[(m0 + j) * 56 + (n0 + i)] = acc[i][j];
    }
    __syncthreads();

    // ---- softmax over keys m (columns), gamma folded into normalization ----
    if (tid < 98) {
        int win = tid / 49;
        int n   = tid - win * 49;
        float* atp = s2 + win * PW + 3920 + n;
        float mx = atp[0];
        #pragma unroll 7
        for (int m = 1; m < NTOK; m++) mx = fmaxf(mx, atp[m * 56]);
        float s = 0.0f;
        #pragma unroll 7
        for (int m = 0; m < NTOK; m++) {
            float e = __expf(atp[m * 56] - mx);
            atp[m * 56] = e;
            s += e;
        }
        float rs = g / s;
        #pragma unroll 7
        for (int m = 0; m < NTOK; m++) atp[m * 56] *= rs;
    }
    __syncthreads();

    // ---- AV: out[n][c] = sum_m att[m][n]*v[m][c], tile 8t x 8c ----
    u64 accA[4][4], accB[4][4];
    int a_win = 0, a_t0 = 0, a_c0 = 0;
    if (tid < 112) {
        a_win = tid / 56;
        int r = tid - a_win * 56;
        int cg = r & 7, tg = r >> 3;
        a_t0 = tg * 8; a_c0 = cg * 8;
        const float* atb = s2 + a_win * PW + 3920 + a_t0;
        const float* vb  = s2 + a_win * PW + 16 + a_c0;
        #pragma unroll
        for (int p = 0; p < 4; p++)
            #pragma unroll
            for (int q = 0; q < 4; q++) { accA[p][q] = 0ull; accB[p][q] = 0ull; }
        #pragma unroll 2
        for (int m = 0; m < NTOK; m++) {
            const u64* ar = reinterpret_cast<const u64*>(atb + m * 56);
            const u64* vr = reinterpret_cast<const u64*>(vb + m * NOUT);
            u64 av[4];
            #pragma unroll
            for (int p = 0; p < 4; p++) av[p] = ar[p];
            #pragma unroll
            for (int q = 0; q < 4; q++) {
                u64 vn = vr[q];
                u64 vs = f2swap(vn);
                #pragma unroll
                for (int p = 0; p < 4; p++) {
                    ffma2(accA[p][q], av[p], vn);
                    ffma2(accB[p][q], av[p], vs);
                }
            }
        }
    }
    __syncthreads();   // all att/v reads done before os overlays the qkv region

    if (tid < 112) {
        float* osp = s2 + a_win * PW;   // os[t][c] stride 66 (over dead qkv)
        #pragma unroll
        for (int p = 0; p < 4; p++) {
            int ta = a_t0 + 2 * p, tb = ta + 1;
            if (ta < NTOK) {
                #pragma unroll
                for (int q = 0; q < 4; q++)
                    *reinterpret_cast<float2*>(osp + ta * OS_STRIDE + a_c0 + 2*q)
                        = make_float2(f2lo(accA[p][q]), f2lo(accB[p][q]));
            }
            if (tb < NTOK) {
                #pragma unroll
                for (int q = 0; q < 4; q++)
                    *reinterpret_cast<float2*>(osp + tb * OS_STRIDE + a_c0 + 2*q)
                        = make_float2(f2hi(accB[p][q]), f2hi(accA[p][q]));
            }
        }
    }
    __syncthreads();

    // ---- residual + store: out = os + x (gamma already applied) ----
    if (tid < 112) {
        int ph = tid >> 4, pw = tid & 15;
        if (pw < 14) {
            int win = (pw >= 7);
            int t   = ph * 7 + pw - 7 * win;
            const float* osr = s2 + win * PW + t * OS_STRIDE;
            size_t gi = (size_t)b * CH * HWPIX + (size_t)(h0 + ph) * HWDIM + (w0 + pw);
            #pragma unroll 4
            for (int c = 0; c < CH; c++) {
                out[gi] = osr[c] + __ldg(&x[gi]);
                gi += HWPIX;
            }
        }
    }
}

extern "C" void kernel_launch(void* const* d_in, const int* in_sizes, int n_in,
                              void* d_out, int out_size)
{
    const float* x     = (const float*)d_in[0];
    const float* Wq    = (const float*)d_in[1];
    const float* bq    = (const float*)d_in[2];
    const float* Wk    = (const float*)d_in[3];
    const float* bk    = (const float*)d_in[4];
    const float* Wv    = (const float*)d_in[5];
    const float* bv    = (const float*)d_in[6];
    const float* gamma = (const float*)d_in[7];
    float* out = (float*)d_out;

    cudaFuncSetAttribute(proj_kernel, cudaFuncAttributeMaxDynamicSharedMemorySize, K1_SMEM_BYTES);
    cudaFuncSetAttribute(attn_kernel, cudaFuncAttributeMaxDynamicSharedMemorySize, K2_SMEM_BYTES);

    proj_kernel<<<NB * (HWPIX / 128), 128, K1_SMEM_BYTES>>>(x, Wq, bq, Wk, bk, Wv, bv);
    attn_kernel<<<NB * 32 * 16, 128, K2_SMEM_BYTES>>>(x, gamma, out);
}

// round 9
// speedup vs baseline: 1.4103x; 1.0917x over previous
#include <cuda_runtime.h>
#include <cstdint>

typedef unsigned long long u64;
typedef unsigned int u32;

#define HWDIM 224
#define HWPIX (HWDIM*HWDIM)   // 50176
#define NB    16
#define NTOK  49
#define CH    64
#define NOUT  80               // q(0..7) k(8..15) v(16..79)

// scratch: pixel-linear qkv [b][hw][80]
__device__ float g_qkv[(size_t)NB * HWPIX * NOUT];

__device__ __forceinline__ float tf32r(float f){
    u32 r;
    asm("cvt.rna.tf32.f32 %0, %1;" : "=r"(r) : "f"(f));
    return __uint_as_float(r);
}
__device__ __forceinline__ void mma_tf32(float* d, const u32* a, u32 b0, u32 b1){
    asm volatile(
        "mma.sync.aligned.m16n8k8.row.col.f32.tf32.tf32.f32 "
        "{%0,%1,%2,%3}, {%4,%5,%6,%7}, {%8,%9}, {%0,%1,%2,%3};"
        : "+f"(d[0]), "+f"(d[1]), "+f"(d[2]), "+f"(d[3])
        : "r"(a[0]), "r"(a[1]), "r"(a[2]), "r"(a[3]), "r"(b0), "r"(b1));
}

// ===================== K1: fused QKV projection (tf32 tensor cores) ===========
// 128 threads, 128 pixels/block. Warp = 32 px x 80 outs (2 m-tiles x 10 n-tiles).
// smem floats: wct[64][82]@0 (5248, tf32) | xt[128][66]@5248 (8448, tf32) | bias@13696 (80)
// epilogue: os[128][80] overlays [0..10240)
#define WCT_S 82
#define XT_S  66
#define OFF_XT   5248
#define OFF_BIAS 13696
#define K1_SMEM_FLOATS 13776
#define K1_SMEM_BYTES  (K1_SMEM_FLOATS*4)   // 55104

__global__ void __launch_bounds__(128, 4)
proj_kernel(const float* __restrict__ x,
            const float* __restrict__ Wq, const float* __restrict__ bq,
            const float* __restrict__ Wk, const float* __restrict__ bk,
            const float* __restrict__ Wv, const float* __restrict__ bv)
{
    extern __shared__ float s1[];
    const int tid = threadIdx.x;
    const int blk = blockIdx.x;               // 16 * 392
    const int b   = blk / 392;
    const int hw0 = (blk - b * 392) * 128;

    // weights -> wct[c][82], tf32-rounded; cols: q(0..7) k(8..15) v(16..79)
    for (int idx = tid; idx < 512; idx += 128) {
        int o = idx >> 6, c = idx & 63;
        s1[c * WCT_S + o]     = tf32r(__ldg(&Wq[idx]));
        s1[c * WCT_S + 8 + o] = tf32r(__ldg(&Wk[idx]));
    }
    for (int idx = tid; idx < 4096; idx += 128) {
        int o = idx >> 6, c = idx & 63;
        s1[c * WCT_S + 16 + o] = tf32r(__ldg(&Wv[idx]));
    }
    if (tid < 80)
        s1[OFF_BIAS + tid] = (tid < 8)  ? __ldg(&bq[tid])
                           : (tid < 16) ? __ldg(&bk[tid - 8])
                                        : __ldg(&bv[tid - 16]);
    // x tile -> xt[p][66], tf32-rounded (transposed store)
    const float* xb = x + (size_t)b * CH * HWPIX + hw0;
    for (int idx = tid; idx < 2048; idx += 128) {
        int c = idx >> 5, p4 = idx & 31;
        float4 v = __ldg(reinterpret_cast<const float4*>(xb + (size_t)c * HWPIX) + p4);
        float* xp = s1 + OFF_XT + (p4 * 4) * XT_S + c;
        xp[0]        = tf32r(v.x);
        xp[XT_S]     = tf32r(v.y);
        xp[2 * XT_S] = tf32r(v.z);
        xp[3 * XT_S] = tf32r(v.w);
    }
    __syncthreads();

    // compute: warp covers px [wid*32, wid*32+32)
    const int wid  = tid >> 5, lane = tid & 31;
    const int grp  = lane >> 2;        // 0..7
    const int tig  = lane & 3;         // 0..3
    const int pb   = wid * 32;

    float d[2][10][4];
    #pragma unroll
    for (int mt = 0; mt < 2; mt++)
        #pragma unroll
        for (int nt = 0; nt < 10; nt++)
            #pragma unroll
            for (int e = 0; e < 4; e++) d[mt][nt][e] = 0.0f;

    const u32* xtu = reinterpret_cast<const u32*>(s1 + OFF_XT);
    const u32* wcu = reinterpret_cast<const u32*>(s1);

    #pragma unroll
    for (int k0 = 0; k0 < 64; k0 += 8) {
        u32 a[2][4];
        #pragma unroll
        for (int mt = 0; mt < 2; mt++) {
            int base = pb + mt * 16;
            a[mt][0] = xtu[(base + grp)     * XT_S + k0 + tig];
            a[mt][1] = xtu[(base + grp + 8) * XT_S + k0 + tig];
            a[mt][2] = xtu[(base + grp)     * XT_S + k0 + tig + 4];
            a[mt][3] = xtu[(base + grp + 8) * XT_S + k0 + tig + 4];
        }
        #pragma unroll
        for (int nt = 0; nt < 10; nt++) {
            u32 b0 = wcu[(k0 + tig)     * WCT_S + nt * 8 + grp];
            u32 b1 = wcu[(k0 + tig + 4) * WCT_S + nt * 8 + grp];
            mma_tf32(d[0][nt], a[0], b0, b1);
            mma_tf32(d[1][nt], a[1], b0, b1);
        }
    }
    __syncthreads();   // xt/wct reads done; os overlays them

    // epilogue: os[p][80] = d + bias
    const float* sb = s1 + OFF_BIAS;
    #pragma unroll
    for (int mt = 0; mt < 2; mt++) {
        int p0 = pb + mt * 16 + grp;
        #pragma unroll
        for (int nt = 0; nt < 10; nt++) {
            int n0 = nt * 8 + 2 * tig;
            float b0v = sb[n0], b1v = sb[n0 + 1];
            *reinterpret_cast<float2*>(s1 + p0 * 80 + n0)
                = make_float2(d[mt][nt][0] + b0v, d[mt][nt][1] + b1v);
            *reinterpret_cast<float2*>(s1 + (p0 + 8) * 80 + n0)
                = make_float2(d[mt][nt][2] + b0v, d[mt][nt][3] + b1v);
        }
    }
    __syncthreads();

    // coalesced stream to g_qkv
    float4* dst = reinterpret_cast<float4*>(g_qkv + ((size_t)b * HWPIX + hw0) * NOUT);
    const float4* src = reinterpret_cast<const float4*>(s1);
    for (int i = tid; i < 2560; i += 128) dst[i] = src[i];
}

// ===================== K2: windowed attention (tf32 tensor cores) =============
// 128 threads, 2 windows/block; 2 warps per window.
// pool/window (6768 floats): qkv[49][80]@0 (3920) | att[49][58]@3920 (2842->2848)
// os[49][66] overlays qkv region (dead after AV).
#define PW 6768
#define AT_S 58
#define ATT_OFF 3920
#define OS_STRIDE 66
#define K2_SMEM_FLOATS (2*PW)
#define K2_SMEM_BYTES  (K2_SMEM_FLOATS*4)   // 54144

__global__ void __launch_bounds__(128, 4)
attn_kernel(const float* __restrict__ x,
            const float* __restrict__ gamma,
            float* __restrict__ out)
{
    extern __shared__ float s2[];
    const int tid = threadIdx.x;
    const int blk = blockIdx.x;        // 16 b * 32 wh * 16 wpair
    const int b   = blk >> 9;
    const int rem = blk & 511;
    const int wh  = rem >> 4;
    const int wp  = rem & 15;
    const int h0  = wh * 7;
    const int w0  = wp * 14;

    const float g = __ldg(gamma);

    const int wid  = tid >> 5, lane = tid & 31;
    const int grp  = lane >> 2, tig = lane & 3;
    const int win  = wid >> 1;                 // window of this warp
    const int half = wid & 1;                  // m-tile half {0,1} vs {2,3}

    float* pool = s2 + win * PW;
    float* att  = pool + ATT_OFF;              // [49][58]
    const u32* pu = reinterpret_cast<const u32*>(pool);

    // ---- stage qkv: 7 rows of 14px*80 contiguous floats ----
    const float* gq = g_qkv + ((size_t)b * HWPIX + (size_t)h0 * HWDIM + w0) * NOUT;
    for (int i = tid; i < 1960; i += 128) {
        int ph = i / 280;
        int rr = i - ph * 280;
        int pw = rr / 20;
        int c4 = rr - pw * 20;
        int wn = (pw >= 7);
        int t  = ph * 7 + pw - 7 * wn;
        float4 v = __ldg(reinterpret_cast<const float4*>(gq + ((size_t)ph * HWDIM + pw) * NOUT) + c4);
        *reinterpret_cast<float4*>(s2 + wn * PW + t * NOUT + c4 * 4) = v;
    }
    // zero att pad cols m = 49..55 (read as A-operand zeros in AV)
    for (int i = tid; i < 686; i += 128) {
        int wn = i / 343;
        int r  = i - wn * 343;
        int n  = r / 7, j = r - n * 7;
        s2[wn * PW + ATT_OFF + n * AT_S + 49 + j] = 0.0f;
    }
    __syncthreads();

    // ---- QK^T: att[n][m] = <q_n, k_m>, mma m16n8k8 (K=8, one step) ----
    {
        #pragma unroll
        for (int mt = 0; mt < 2; mt++) {
            int r0 = (half * 2 + mt) * 16 + grp;
            int r1 = r0 + 8;
            int r0c = min(r0, 48), r1c = min(r1, 48);
            u32 a[4];
            a[0] = pu[r0c * NOUT + tig];
            a[1] = pu[r1c * NOUT + tig];
            a[2] = pu[r0c * NOUT + tig + 4];
            a[3] = pu[r1c * NOUT + tig + 4];
            float dq[7][4];
            #pragma unroll
            for (int nt = 0; nt < 7; nt++)
                #pragma unroll
                for (int e = 0; e < 4; e++) dq[nt][e] = 0.0f;
            #pragma unroll
            for (int nt = 0; nt < 7; nt++) {
                int m = nt * 8 + grp;
                u32 b0 = 0, b1 = 0;
                if (m < NTOK) {
                    b0 = pu[m * NOUT + 8 + tig];
                    b1 = pu[m * NOUT + 8 + tig + 4];
                }
                mma_tf32(dq[nt], a, b0, b1);
            }
            // store logits (predicated on real rows/cols)
            #pragma unroll
            for (int nt = 0; nt < 7; nt++) {
                int c0 = nt * 8 + 2 * tig;
                if (r0 < NTOK) {
                    if (c0 < NTOK)     att[r0 * AT_S + c0]     = dq[nt][0];
                    if (c0 + 1 < NTOK) att[r0 * AT_S + c0 + 1] = dq[nt][1];
                }
                if (r1 < NTOK) {
                    if (c0 < NTOK)     att[r1 * AT_S + c0]     = dq[nt][2];
                    if (c0 + 1 < NTOK) att[r1 * AT_S + c0 + 1] = dq[nt][3];
                }
            }
        }
    }
    __syncthreads();

    // ---- softmax over keys m (rows of att), gamma folded ----
    {
        int row = half * 32 + lane;    // 0..63 per window
        if (row < NTOK) {
            float* ar = att + row * AT_S;
            float mx = ar[0];
            #pragma unroll 7
            for (int m = 1; m < NTOK; m++) mx = fmaxf(mx, ar[m]);
            float s = 0.0f;
            #pragma unroll 7
            for (int m = 0; m < NTOK; m++) {
                float e = __expf(ar[m] - mx);
                ar[m] = e;
                s += e;
            }
            float rs = g / s;
            #pragma unroll 7
            for (int m = 0; m < NTOK; m++) ar[m] = tf32r(ar[m] * rs);
        }
    }
    __syncthreads();

    // ---- AV: out[n][c] = sum_m att[n][m] * v[m][c], mma over K=56 (7 steps) ----
    float dv[2][8][4];
    #pragma unroll
    for (int mt = 0; mt < 2; mt++)
        #pragma unroll
        for (int nt = 0; nt < 8; nt++)
            #pragma unroll
            for (int e = 0; e < 4; e++) dv[mt][nt][e] = 0.0f;

    {
        const u32* au = reinterpret_cast<const u32*>(att);
        int r0 = (half * 2) * 16 + grp;        // mt=0 row
        int r0c = min(r0, 48), r1c = min(r0 + 8, 48);
        int r2c = min(r0 + 16, 48), r3c = min(r0 + 24, 48);
        #pragma unroll
        for (int ks = 0; ks < 7; ks++) {
            int k0 = ks * 8;
            u32 a0[4], a1[4];
            a0[0] = au[r0c * AT_S + k0 + tig];
            a0[1] = au[r1c * AT_S + k0 + tig];
            a0[2] = au[r0c * AT_S + k0 + tig + 4];
            a0[3] = au[r1c * AT_S + k0 + tig + 4];
            a1[0] = au[r2c * AT_S + k0 + tig];
            a1[1] = au[r3c * AT_S + k0 + tig];
            a1[2] = au[r2c * AT_S + k0 + tig + 4];
            a1[3] = au[r3c * AT_S + k0 + tig + 4];
            #pragma unroll
            for (int nt = 0; nt < 8; nt++) {
                int c = nt * 8 + grp;
                u32 b0 = 0, b1 = 0;
                int m0 = k0 + tig;
                if (ks < 6) {
                    b0 = pu[m0 * NOUT + 16 + c];
                    b1 = pu[(m0 + 4) * NOUT + 16 + c];
                } else {
                    if (m0 < NTOK) b0 = pu[m0 * NOUT + 16 + c];  // only m=48
                }
                mma_tf32(dv[0][nt], a0, b0, b1);
                mma_tf32(dv[1][nt], a1, b0, b1);
            }
        }
    }
    __syncthreads();   // all att/V reads done before os overlays qkv

    // ---- epilogue: os[t][66] over dead qkv ----
    {
        #pragma unroll
        for (int mt = 0; mt < 2; mt++) {
            int r0 = (half * 2 + mt) * 16 + grp;
            int r1 = r0 + 8;
            #pragma unroll
            for (int nt = 0; nt < 8; nt++) {
                int c0 = nt * 8 + 2 * tig;
                if (r0 < NTOK)
                    *reinterpret_cast<float2*>(pool + r0 * OS_STRIDE + c0)
                        = make_float2(dv[mt][nt][0], dv[mt][nt][1]);
                if (r1 < NTOK)
                    *reinterpret_cast<float2*>(pool + r1 * OS_STRIDE + c0)
                        = make_float2(dv[mt][nt][2], dv[mt][nt][3]);
            }
        }
    }
    __syncthreads();

    // ---- residual + store: out = os + x (gamma already applied) ----
    if (tid < 112) {
        int ph = tid >> 4, pw = tid & 15;
        if (pw < 14) {
            int wn = (pw >= 7);
            int t  = ph * 7 + pw - 7 * wn;
            const float* osr = s2 + wn * PW + t * OS_STRIDE;
            size_t gi = (size_t)b * CH * HWPIX + (size_t)(h0 + ph) * HWDIM + (w0 + pw);
            #pragma unroll 4
            for (int c = 0; c < CH; c++) {
                out[gi] = osr[c] + __ldg(&x[gi]);
                gi += HWPIX;
            }
        }
    }
}

extern "C" void kernel_launch(void* const* d_in, const int* in_sizes, int n_in,
                              void* d_out, int out_size)
{
    const float* x     = (const float*)d_in[0];
    const float* Wq    = (const float*)d_in[1];
    const float* bq    = (const float*)d_in[2];
    const float* Wk    = (const float*)d_in[3];
    const float* bk    = (const float*)d_in[4];
    const float* Wv    = (const float*)d_in[5];
    const float* bv    = (const float*)d_in[6];
    const float* gamma = (const float*)d_in[7];
    float* out = (float*)d_out;

    cudaFuncSetAttribute(proj_kernel, cudaFuncAttributeMaxDynamicSharedMemorySize, K1_SMEM_BYTES);
    cudaFuncSetAttribute(attn_kernel, cudaFuncAttributeMaxDynamicSharedMemorySize, K2_SMEM_BYTES);

    proj_kernel<<<NB * (HWPIX / 128), 128, K1_SMEM_BYTES>>>(x, Wq, bq, Wk, bk, Wv, bv);
    attn_kernel<<<NB * 32 * 16, 128, K2_SMEM_BYTES>>>(x, gamma, out);
}

// round 10
// speedup vs baseline: 1.4363x; 1.0184x over previous
#include <cuda_runtime.h>
#include <cstdint>

typedef unsigned long long u64;
typedef unsigned int u32;

#define HWDIM 224
#define HWPIX (HWDIM*HWDIM)   // 50176
#define NB    16
#define NTOK  49
#define CH    64
#define NOUT  80               // q(0..7) k(8..15) v(16..79)

// scratch: pixel-linear qkv [b][hw][80]
__device__ float g_qkv[(size_t)NB * HWPIX * NOUT];

__device__ __forceinline__ float tf32r(float f){
    u32 r;
    asm("cvt.rna.tf32.f32 %0, %1;" : "=r"(r) : "f"(f));
    return __uint_as_float(r);
}
__device__ __forceinline__ void mma_tf32(float* d, const u32* a, u32 b0, u32 b1){
    asm volatile(
        "mma.sync.aligned.m16n8k8.row.col.f32.tf32.tf32.f32 "
        "{%0,%1,%2,%3}, {%4,%5,%6,%7}, {%8,%9}, {%0,%1,%2,%3};"
        : "+f"(d[0]), "+f"(d[1]), "+f"(d[2]), "+f"(d[3])
        : "r"(a[0]), "r"(a[1]), "r"(a[2]), "r"(a[3]), "r"(b0), "r"(b1));
}

// ===================== K1: fused QKV projection (tf32 tensor cores) ===========
// (unchanged from round 9)
#define WCT_S 82
#define XT_S  66
#define OFF_XT   5248
#define OFF_BIAS 13696
#define K1_SMEM_FLOATS 13776
#define K1_SMEM_BYTES  (K1_SMEM_FLOATS*4)   // 55104

__global__ void __launch_bounds__(128, 4)
proj_kernel(const float* __restrict__ x,
            const float* __restrict__ Wq, const float* __restrict__ bq,
            const float* __restrict__ Wk, const float* __restrict__ bk,
            const float* __restrict__ Wv, const float* __restrict__ bv)
{
    extern __shared__ float s1[];
    const int tid = threadIdx.x;
    const int blk = blockIdx.x;               // 16 * 392
    const int b   = blk / 392;
    const int hw0 = (blk - b * 392) * 128;

    for (int idx = tid; idx < 512; idx += 128) {
        int o = idx >> 6, c = idx & 63;
        s1[c * WCT_S + o]     = tf32r(__ldg(&Wq[idx]));
        s1[c * WCT_S + 8 + o] = tf32r(__ldg(&Wk[idx]));
    }
    for (int idx = tid; idx < 4096; idx += 128) {
        int o = idx >> 6, c = idx & 63;
        s1[c * WCT_S + 16 + o] = tf32r(__ldg(&Wv[idx]));
    }
    if (tid < 80)
        s1[OFF_BIAS + tid] = (tid < 8)  ? __ldg(&bq[tid])
                           : (tid < 16) ? __ldg(&bk[tid - 8])
                                        : __ldg(&bv[tid - 16]);
    const float* xb = x + (size_t)b * CH * HWPIX + hw0;
    for (int idx = tid; idx < 2048; idx += 128) {
        int c = idx >> 5, p4 = idx & 31;
        float4 v = __ldg(reinterpret_cast<const float4*>(xb + (size_t)c * HWPIX) + p4);
        float* xp = s1 + OFF_XT + (p4 * 4) * XT_S + c;
        xp[0]        = tf32r(v.x);
        xp[XT_S]     = tf32r(v.y);
        xp[2 * XT_S] = tf32r(v.z);
        xp[3 * XT_S] = tf32r(v.w);
    }
    __syncthreads();

    const int wid  = tid >> 5, lane = tid & 31;
    const int grp  = lane >> 2;
    const int tig  = lane & 3;
    const int pb   = wid * 32;

    float d[2][10][4];
    #pragma unroll
    for (int mt = 0; mt < 2; mt++)
        #pragma unroll
        for (int nt = 0; nt < 10; nt++)
            #pragma unroll
            for (int e = 0; e < 4; e++) d[mt][nt][e] = 0.0f;

    const u32* xtu = reinterpret_cast<const u32*>(s1 + OFF_XT);
    const u32* wcu = reinterpret_cast<const u32*>(s1);

    #pragma unroll
    for (int k0 = 0; k0 < 64; k0 += 8) {
        u32 a[2][4];
        #pragma unroll
        for (int mt = 0; mt < 2; mt++) {
            int base = pb + mt * 16;
            a[mt][0] = xtu[(base + grp)     * XT_S + k0 + tig];
            a[mt][1] = xtu[(base + grp + 8) * XT_S + k0 + tig];
            a[mt][2] = xtu[(base + grp)     * XT_S + k0 + tig + 4];
            a[mt][3] = xtu[(base + grp + 8) * XT_S + k0 + tig + 4];
        }
        #pragma unroll
        for (int nt = 0; nt < 10; nt++) {
            u32 b0 = wcu[(k0 + tig)     * WCT_S + nt * 8 + grp];
            u32 b1 = wcu[(k0 + tig + 4) * WCT_S + nt * 8 + grp];
            mma_tf32(d[0][nt], a[0], b0, b1);
            mma_tf32(d[1][nt], a[1], b0, b1);
        }
    }
    __syncthreads();

    const float* sb = s1 + OFF_BIAS;
    #pragma unroll
    for (int mt = 0; mt < 2; mt++) {
        int p0 = pb + mt * 16 + grp;
        #pragma unroll
        for (int nt = 0; nt < 10; nt++) {
            int n0 = nt * 8 + 2 * tig;
            float b0v = sb[n0], b1v = sb[n0 + 1];
            *reinterpret_cast<float2*>(s1 + p0 * 80 + n0)
                = make_float2(d[mt][nt][0] + b0v, d[mt][nt][1] + b1v);
            *reinterpret_cast<float2*>(s1 + (p0 + 8) * 80 + n0)
                = make_float2(d[mt][nt][2] + b0v, d[mt][nt][3] + b1v);
        }
    }
    __syncthreads();

    float4* dst = reinterpret_cast<float4*>(g_qkv + ((size_t)b * HWPIX + hw0) * NOUT);
    const float4* src = reinterpret_cast<const float4*>(s1);
    for (int i = tid; i < 2560; i += 128) dst[i] = src[i];
}

// ===================== K2: windowed attention (tf32, 1 window / 64 thr) =======
// 64 threads = 2 warps, 1 window; 8 blocks/SM (16 warps), 3 block barriers.
// smem (6768 floats): qkv[49][80]@0 (3920) | att[49][58]@3920 (2842->2848)
// os[49][66] overlays qkv region after AV.
#define AT_S 58
#define ATT_OFF 3920
#define OS_STRIDE 66
#define K2_SMEM_FLOATS 6768
#define K2_SMEM_BYTES  (K2_SMEM_FLOATS*4)   // 27072

__global__ void __launch_bounds__(64, 8)
attn_kernel(const float* __restrict__ x,
            const float* __restrict__ gamma,
            float* __restrict__ out)
{
    extern __shared__ float sp[];
    const int tid = threadIdx.x;
    const int blk = blockIdx.x;        // 16 b * 32 wh * 32 ww
    const int b   = blk >> 10;
    const int rem = blk & 1023;
    const int wh  = rem >> 5;
    const int ww  = rem & 31;
    const int h0  = wh * 7;
    const int w0  = ww * 7;

    const float g = __ldg(gamma);

    const int wid  = tid >> 5, lane = tid & 31;
    const int grp  = lane >> 2, tig = lane & 3;
    const int half = wid;              // m-tile half {0,1}

    float* att = sp + ATT_OFF;         // [49][58]
    const u32* pu = reinterpret_cast<const u32*>(sp);

    // ---- stage qkv: 49 px * 20 float4, contiguous per pixel row ----
    const float* gq = g_qkv + ((size_t)b * HWPIX + (size_t)h0 * HWDIM + w0) * NOUT;
    for (int i = tid; i < 980; i += 64) {
        int ph = i / 140;
        int rr = i - ph * 140;
        int pw = rr / 20;
        int c4 = rr - pw * 20;
        int t  = ph * 7 + pw;
        float4 v = __ldg(reinterpret_cast<const float4*>(gq + ((size_t)ph * HWDIM + pw) * NOUT) + c4);
        *reinterpret_cast<float4*>(sp + t * NOUT + c4 * 4) = v;
    }
    // zero att pad cols m = 49..55 (A-operand zeros in AV)
    for (int i = tid; i < 343; i += 64) {
        int n = i / 7, j = i - n * 7;
        att[n * AT_S + 49 + j] = 0.0f;
    }
    __syncthreads();   // barrier 1: all q/k/v + pads visible

    // ---- QK^T: att[n][m] = <q_n, k_m>  (rows warp-local to `half`) ----
    #pragma unroll
    for (int mt = 0; mt < 2; mt++) {
        int r0 = (half * 2 + mt) * 16 + grp;
        int r1 = r0 + 8;
        int r0c = min(r0, 48), r1c = min(r1, 48);
        u32 a[4];
        a[0] = pu[r0c * NOUT + tig];
        a[1] = pu[r1c * NOUT + tig];
        a[2] = pu[r0c * NOUT + tig + 4];
        a[3] = pu[r1c * NOUT + tig + 4];
        float dq[7][4];
        #pragma unroll
        for (int nt = 0; nt < 7; nt++)
            #pragma unroll
            for (int e = 0; e < 4; e++) dq[nt][e] = 0.0f;
        #pragma unroll
        for (int nt = 0; nt < 7; nt++) {
            int m = nt * 8 + grp;
            u32 b0 = 0, b1 = 0;
            if (m < NTOK) {
                b0 = pu[m * NOUT + 8 + tig];
                b1 = pu[m * NOUT + 8 + tig + 4];
            }
            mma_tf32(dq[nt], a, b0, b1);
        }
        #pragma unroll
        for (int nt = 0; nt < 7; nt++) {
            int c0 = nt * 8 + 2 * tig;
            if (r0 < NTOK) {
                if (c0 < NTOK)     att[r0 * AT_S + c0]     = dq[nt][0];
                if (c0 + 1 < NTOK) att[r0 * AT_S + c0 + 1] = dq[nt][1];
            }
            if (r1 < NTOK) {
                if (c0 < NTOK)     att[r1 * AT_S + c0]     = dq[nt][2];
                if (c0 + 1 < NTOK) att[r1 * AT_S + c0 + 1] = dq[nt][3];
            }
        }
    }
    __syncwarp();      // rows are warp-local; no block barrier needed

    // ---- softmax over keys m (rows of att), gamma folded ----
    {
        int row = half * 32 + lane;
        if (row < NTOK) {
            float* ar = att + row * AT_S;
            float mx = ar[0];
            #pragma unroll 7
            for (int m = 1; m < NTOK; m++) mx = fmaxf(mx, ar[m]);
            float s = 0.0f;
            #pragma unroll 7
            for (int m = 0; m < NTOK; m++) {
                float e = __expf(ar[m] - mx);
                ar[m] = e;
                s += e;
            }
            float rs = g / s;
            #pragma unroll 7
            for (int m = 0; m < NTOK; m++) ar[m] = tf32r(ar[m] * rs);
        }
    }
    __syncwarp();      // still warp-local

    // ---- AV: out[n][c] = sum_m att[n][m] * v[m][c]  (A rows warp-local) ----
    float dv[2][8][4];
    #pragma unroll
    for (int mt = 0; mt < 2; mt++)
        #pragma unroll
        for (int nt = 0; nt < 8; nt++)
            #pragma unroll
            for (int e = 0; e < 4; e++) dv[mt][nt][e] = 0.0f;

    {
        const u32* au = reinterpret_cast<const u32*>(att);
        int r0 = (half * 2) * 16 + grp;
        int r0c = min(r0, 48), r1c = min(r0 + 8, 48);
        int r2c = min(r0 + 16, 48), r3c = min(r0 + 24, 48);
        #pragma unroll
        for (int ks = 0; ks < 7; ks++) {
            int k0 = ks * 8;
            u32 a0[4], a1[4];
            a0[0] = au[r0c * AT_S + k0 + tig];
            a0[1] = au[r1c * AT_S + k0 + tig];
            a0[2] = au[r0c * AT_S + k0 + tig + 4];
            a0[3] = au[r1c * AT_S + k0 + tig + 4];
            a1[0] = au[r2c * AT_S + k0 + tig];
            a1[1] = au[r3c * AT_S + k0 + tig];
            a1[2] = au[r2c * AT_S + k0 + tig + 4];
            a1[3] = au[r3c * AT_S + k0 + tig + 4];
            #pragma unroll
            for (int nt = 0; nt < 8; nt++) {
                int c = nt * 8 + grp;
                u32 b0 = 0, b1 = 0;
                int m0 = k0 + tig;
                if (ks < 6) {
                    b0 = pu[m0 * NOUT + 16 + c];
                    b1 = pu[(m0 + 4) * NOUT + 16 + c];
                } else {
                    if (m0 < NTOK) b0 = pu[m0 * NOUT + 16 + c];  // only m=48
                }
                mma_tf32(dv[0][nt], a0, b0, b1);
                mma_tf32(dv[1][nt], a1, b0, b1);
            }
        }
    }
    __syncthreads();   // barrier 2: both warps' V reads done before os overlays qkv

    // ---- epilogue: os[t][66] over dead qkv ----
    #pragma unroll
    for (int mt = 0; mt < 2; mt++) {
        int r0 = (half * 2 + mt) * 16 + grp;
        int r1 = r0 + 8;
        #pragma unroll
        for (int nt = 0; nt < 8; nt++) {
            int c0 = nt * 8 + 2 * tig;
            if (r0 < NTOK)
                *reinterpret_cast<float2*>(sp + r0 * OS_STRIDE + c0)
                    = make_float2(dv[mt][nt][0], dv[mt][nt][1]);
            if (r1 < NTOK)
                *reinterpret_cast<float2*>(sp + r1 * OS_STRIDE + c0)
                    = make_float2(dv[mt][nt][2], dv[mt][nt][3]);
        }
    }
    __syncthreads();   // barrier 3: os complete

    // ---- residual + store: out = os + x (gamma already applied) ----
    for (int u = tid; u < 98; u += 64) {
        int p  = u >> 1;
        int ch = (u & 1) * 32;
        int ph = p / 7, pw = p - ph * 7;
        const float* osr = sp + p * OS_STRIDE + ch;
        size_t gi = (size_t)b * CH * HWPIX + (size_t)(h0 + ph) * HWDIM + (w0 + pw)
                  + (size_t)ch * HWPIX;
        #pragma unroll 8
        for (int c = 0; c < 32; c++) {
            out[gi] = osr[c] + __ldg(&x[gi]);
            gi += HWPIX;
        }
    }
}

extern "C" void kernel_launch(void* const* d_in, const int* in_sizes, int n_in,
                              void* d_out, int out_size)
{
    const float* x     = (const float*)d_in[0];
    const float* Wq    = (const float*)d_in[1];
    const float* bq    = (const float*)d_in[2];
    const float* Wk    = (const float*)d_in[3];
    const float* bk    = (const float*)d_in[4];
    const float* Wv    = (const float*)d_in[5];
    const float* bv    = (const float*)d_in[6];
    const float* gamma = (const float*)d_in[7];
    float* out = (float*)d_out;

    cudaFuncSetAttribute(proj_kernel, cudaFuncAttributeMaxDynamicSharedMemorySize, K1_SMEM_BYTES);
    cudaFuncSetAttribute(attn_kernel, cudaFuncAttributeMaxDynamicSharedMemorySize, K2_SMEM_BYTES);

    proj_kernel<<<NB * (HWPIX / 128), 128, K1_SMEM_BYTES>>>(x, Wq, bq, Wk, bk, Wv, bv);
    attn_kernel<<<NB * 1024, 64, K2_SMEM_BYTES>>>(x, gamma, out);
}